// round 2
// baseline (speedup 1.0000x reference)
#include <cuda_runtime.h>
#include <cuda_bf16.h>

// Problem constants (fixed by the dataset shapes)
#define BB   16
#define KK   64
#define HH   160
#define WW   160
#define HWC  (HH * WW)          // 25600
#define NTHR WW                 // one block = one image row (5 warps)
#define EPS_F 1e-5f

__device__ __forceinline__ float ex2_approx(float x) {
    float r;
    asm("ex2.approx.ftz.f32 %0, %1;" : "=f"(r) : "f"(x));
    return r;
}

__global__ __launch_bounds__(NTHR)
void recon_conf_map_kernel(const float* __restrict__ kp,    // [B,K,2] (x,y)
                           const float* __restrict__ psx,   // scalar
                           const float* __restrict__ psy,   // scalar
                           const float* __restrict__ prho,  // scalar
                           float* __restrict__ out)         // [B,K,H,W]
{
    // Per-(k,row) quadratic coefficients: e(fx) = Bq*fx^2 + q.y*fx + q.x
    __shared__ float2 sq[KK];

    const int b = blockIdx.x / HH;
    const int y = blockIdx.x % HH;

    // Scalars (broadcast LDG, L1-cached)
    const float sx  = psx[0];
    const float sy  = psy[0];
    const float rho = prho[0];

    const float omr2 = 1.0f - rho * rho;
    const float num1 = -0.5f / omr2;
    const float L2E  = 1.4426950408889634f;           // log2(e)
    const float den  = 1.0f / (6.2831853071795864f * sx * sy * sqrtf(omr2));
    const float l2den = log2f(den);

    // base-2 exponent = A*dy^2 + Bq*dx^2 + C*dy*dx  (+ l2den folded in)
    const float A  = num1 * L2E / (sy * sy);
    const float Bq = num1 * L2E / (sx * sx);
    const float C  = num1 * L2E * (-2.0f * rho) / (sx * sy);

    // Precompute per-k 1-D quadratic for this row:
    //   dy = y - ky, dx = fx - kx
    //   e  = A*dy^2 + Bq*(fx-kx)^2 + C*dy*(fx-kx) + l2den
    //      = Bq*fx^2 + (C*dy - 2*Bq*kx)*fx + [A*dy^2 + Bq*kx^2 - (C*dy)*kx + l2den]
    if (threadIdx.x < KK) {
        float2 p = reinterpret_cast<const float2*>(kp)[b * KK + threadIdx.x];
        const float kx = p.x;
        const float dy = (float)y - p.y;
        const float cy = C * dy;
        const float ay = fmaf(A * dy, dy, l2den);
        const float q1 = fmaf(-2.0f * Bq, kx, cy);
        const float q0 = fmaf(kx, fmaf(Bq, kx, -cy), ay);
        sq[threadIdx.x] = make_float2(q0, q1);
    }
    __syncthreads();

    const float fx   = (float)threadIdx.x;
    const float bfx2 = Bq * fx * fx;

    float vals[KK];
    float sum0 = 0.0f, sum1 = 0.0f;   // two accumulators to shorten dep chain

#pragma unroll
    for (int k = 0; k < KK; k += 2) {
        const float2 qa = sq[k];
        const float2 qb = sq[k + 1];
        const float ea = fmaf(qa.y, fx, qa.x) + bfx2;
        const float eb = fmaf(qb.y, fx, qb.x) + bfx2;
        const float va = ex2_approx(ea);
        const float vb = ex2_approx(eb);
        vals[k]     = va;
        vals[k + 1] = vb;
        sum0 += va;
        sum1 += vb;
    }

    const float inv = __fdividef(1.0f, (sum0 + sum1) + EPS_F);

    // out[b, k, y, x]; each k-store is a coalesced 128B-aligned warp segment
    float* __restrict__ o = out + ((size_t)b * KK + 0) * HWC + (size_t)y * WW + threadIdx.x;
#pragma unroll
    for (int k = 0; k < KK; ++k) {
        o[(size_t)k * HWC] = vals[k] * inv;
    }
}

extern "C" void kernel_launch(void* const* d_in, const int* in_sizes, int n_in,
                              void* d_out, int out_size) {
    // metadata order: keypoints, std_x, std_y, correlation, DetectionMap (unused)
    const float* kp   = (const float*)d_in[0];
    const float* psx  = (const float*)d_in[1];
    const float* psy  = (const float*)d_in[2];
    const float* prho = (const float*)d_in[3];
    float* out = (float*)d_out;

    const int grid = BB * HH;   // 2560 blocks, one per (batch, row)
    recon_conf_map_kernel<<<grid, NTHR>>>(kp, psx, psy, prho, out);
}